// round 16
// baseline (speedup 1.0000x reference)
#include <cuda_runtime.h>
#include <cuda_fp16.h>
#include <cstdint>

#define B_ 32
#define S_ 4096
#define K_ 1024
#define H_ 1024
#define V_ 1024

#define TM 128             // compacted rows per block
#define TN 256             // h columns per pass
#define NPASS (H_ / TN)    // 4
#define HSPLIT 2           // h-passes split across 2 blocks (score is additive in h)
#define KCH 64             // k halves per chunk (128B rows)
#define NCHUNK (K_ / KCH)  // 16
#define SSTRH 72           // smem row stride in halves (64 data + 8 pad = 144B)
#define CSPLIT 128
#define TILES_PER_B (S_ / TM)  // 32
#define NTILES (B_ * TILES_PER_B)  // 1024

#define A_HALFS (TM * SSTRH)   // 9216
#define B_HALFS (TN * SSTRH)   // 18432
#define DSMEM_BYTES ((2 * A_HALFS + 2 * B_HALFS) * 2)  // 110592 B

// fused setup grid split: compact | convert Wk | qproj (mutually independent)
#define COMPACT_BLOCKS 32
#define CONV_BLOCKS    ((H_ * K_) / (256 * 8))   // 512
#define QPROJ_BLOCKS   (B_ * (H_ / 128))         // 256
#define SETUP_BLOCKS (COMPACT_BLOCKS + CONV_BLOCKS + QPROJ_BLOCKS)

// merged gather+scores grid: gather-role first (lower indices schedule first)
#define GS_BLOCKS (NTILES + NTILES * HSPLIT)     // 1024 + 2048

// ---------------- scratch ----------------
__device__ float  g_qproj[B_ * H_];
__device__ float  g_scores[B_ * S_];
__device__ float  g_ctx_part[CSPLIT * B_ * V_];
__device__ int    g_idx[B_ * S_];          // compacted unmasked row indices
__device__ int    g_cnt[B_];               // unmasked count per batch
__device__ int    g_tile_flag[NTILES];     // per-tile gather-done flags
__device__ __half g_keys_h[B_ * S_ * K_];  // gathered fp16 keys (compacted rows)
__device__ __half g_wk_h[H_ * K_];         // fp16 Wk

// ---------------- helpers ----------------
__device__ __forceinline__ void cpa16s(uint32_t s, const void* g) {
    asm volatile("cp.async.cg.shared.global [%0], [%1], 16;" :: "r"(s), "l"(g));
}
__device__ __forceinline__ void cp_commit() { asm volatile("cp.async.commit_group;"); }
template <int N> __device__ __forceinline__ void cp_wait() {
    asm volatile("cp.async.wait_group %0;" :: "n"(N));
}
__device__ __forceinline__ float tanh_mufu(float x) {
    float y;
    asm("tanh.approx.f32 %0, %1;" : "=f"(y) : "f"(x));
    return y;
}
__device__ __forceinline__ void ldsm_x4(uint32_t r[4], uint32_t addr) {
    asm volatile("ldmatrix.sync.aligned.m8n8.x4.shared.b16 {%0,%1,%2,%3}, [%4];"
                 : "=r"(r[0]), "=r"(r[1]), "=r"(r[2]), "=r"(r[3]) : "r"(addr));
}
__device__ __forceinline__ void mma16816(float c[4], const uint32_t a[4],
                                         uint32_t b0, uint32_t b1) {
    asm volatile(
        "mma.sync.aligned.m16n8k16.row.col.f32.f16.f16.f32 "
        "{%0,%1,%2,%3}, {%4,%5,%6,%7}, {%8,%9}, {%0,%1,%2,%3};"
        : "+f"(c[0]), "+f"(c[1]), "+f"(c[2]), "+f"(c[3])
        : "r"(a[0]), "r"(a[1]), "r"(a[2]), "r"(a[3]), "r"(b0), "r"(b1));
}
__device__ __forceinline__ void pack8h(__half* dst, const float4 a, const float4 b) {
    __half2* d = (__half2*)dst;
    d[0] = __floats2half2_rn(a.x, a.y);
    d[1] = __floats2half2_rn(a.z, a.w);
    d[2] = __floats2half2_rn(b.x, b.y);
    d[3] = __floats2half2_rn(b.z, b.w);
}
__device__ __forceinline__ float4 ldcs4(const float4* p) {
    float4 v;
    asm volatile("ld.global.cs.v4.f32 {%0,%1,%2,%3}, [%4];"
                 : "=f"(v.x), "=f"(v.y), "=f"(v.z), "=f"(v.w) : "l"(p));
    return v;
}

// ---------------- kernel 0: fused setup (compact | convert Wk | qproj) ----------
__global__ void setup_kernel(const int* __restrict__ mask,
                             const float* __restrict__ Wk,
                             const float* __restrict__ query,
                             const float* __restrict__ Wq_w,
                             const float* __restrict__ Wq_b,
                             const float* __restrict__ Wk_b) {
    __shared__ float4 q4[K_ / 4];   // qproj segment
    __shared__ int wsum[8];         // compact segment
    __shared__ int sbase;
    int bid = blockIdx.x, tid = threadIdx.x;

    if (bid < COMPACT_BLOCKS) {
        // ---- fill scores (0 / -inf), zero tile flags, deterministic compact ----
        int b = bid, warp = tid >> 5, lane = tid & 31;
        if (tid == 0) sbase = 0;
        if (tid < TILES_PER_B) g_tile_flag[b * TILES_PER_B + tid] = 0;
        __syncthreads();
        const int* mb = mask + b * S_;
        for (int it = 0; it < S_ / 256; it++) {
            int s = it * 256 + tid;
            int m = (mb[s] != 0);
            // unmasked rows start at 0 (split-H partials atomicAdd onto this)
            g_scores[b * S_ + s] = m ? 0.0f : __int_as_float(0xff800000);
            unsigned bal = __ballot_sync(0xffffffffu, m);
            int pre = __popc(bal & ((1u << lane) - 1));
            if (lane == 0) wsum[warp] = __popc(bal);
            __syncthreads();
            int wpre = 0;
            #pragma unroll
            for (int w = 0; w < 8; w++) if (w < warp) wpre += wsum[w];
            if (m) g_idx[b * S_ + sbase + wpre + pre] = s;
            __syncthreads();
            if (tid == 0) {
                int t = 0;
                #pragma unroll
                for (int w = 0; w < 8; w++) t += wsum[w];
                sbase += t;
            }
            __syncthreads();
        }
        if (tid == 0) g_cnt[b] = sbase;
    } else if (bid < COMPACT_BLOCKS + CONV_BLOCKS) {
        // ---- Wk -> fp16 ----
        int i = (bid - COMPACT_BLOCKS) * 256 + tid;
        const float4* sp = (const float4*)(Wk + (size_t)i * 8);
        __half hv[8];
        pack8h(hv, sp[0], sp[1]);
        *(uint4*)(g_wk_h + (size_t)i * 8) = *(uint4*)hv;
    } else {
        // ---- q_proj (fp32 exact, biases folded), float4 + 2-row ILP ----
        int qb = bid - COMPACT_BLOCKS - CONV_BLOCKS;
        int b = qb >> 3, hbase = (qb & 7) * 128;
        for (int i = tid; i < K_ / 4; i += 256)
            q4[i] = ((const float4*)(query + b * K_))[i];
        __syncthreads();
        int warp = tid >> 5, lane = tid & 31;
        #pragma unroll 1
        for (int i = 0; i < 16; i += 2) {
            int h0 = hbase + warp * 16 + i;
            const float4* w0 = (const float4*)(Wq_w + (size_t)h0 * K_);
            const float4* w1 = (const float4*)(Wq_w + (size_t)(h0 + 1) * K_);
            float4 a0 = make_float4(0.f, 0.f, 0.f, 0.f);
            float4 a1 = make_float4(0.f, 0.f, 0.f, 0.f);
            #pragma unroll
            for (int it = 0; it < 8; it++) {
                int kk = it * 32 + lane;
                float4 qv = q4[kk];
                float4 x0 = w0[kk];
                float4 x1 = w1[kk];
                a0.x = fmaf(qv.x, x0.x, a0.x); a0.y = fmaf(qv.y, x0.y, a0.y);
                a0.z = fmaf(qv.z, x0.z, a0.z); a0.w = fmaf(qv.w, x0.w, a0.w);
                a1.x = fmaf(qv.x, x1.x, a1.x); a1.y = fmaf(qv.y, x1.y, a1.y);
                a1.z = fmaf(qv.z, x1.z, a1.z); a1.w = fmaf(qv.w, x1.w, a1.w);
            }
            float s0 = (a0.x + a0.y) + (a0.z + a0.w);
            float s1 = (a1.x + a1.y) + (a1.z + a1.w);
            #pragma unroll
            for (int o = 16; o; o >>= 1) {
                s0 += __shfl_xor_sync(0xffffffffu, s0, o);
                s1 += __shfl_xor_sync(0xffffffffu, s1, o);
            }
            if (lane == 0) {
                g_qproj[b * H_ + h0]     = s0 + Wq_b[h0]     + Wk_b[h0];
                g_qproj[b * H_ + h0 + 1] = s1 + Wq_b[h0 + 1] + Wk_b[h0 + 1];
            }
        }
    }
}

// ---------------- kernel 1: merged gather + scores (flag-pipelined) -------------
// blocks [0, NTILES): gather role (fp32 keys -> fp16 compacted, then release flag)
// blocks [NTILES, GS_BLOCKS): scores role (acquire flag, then R15-proven mainloop)
__global__ __launch_bounds__(512, 1) void gs_kernel(const float* __restrict__ keys,
                                                    const float* __restrict__ v_w) {
    extern __shared__ __half dsmh[];
    __shared__ float qs[TN];
    __shared__ float vs[TN];
    __shared__ float sscore[TM];

    int bidx = blockIdx.x;
    int tid = threadIdx.x;

    if (bidx < NTILES) {
        // ================= gather role =================
        int b = bidx / TILES_PER_B;
        int t = bidx % TILES_PER_B;
        int cnt = g_cnt[b];
        if (t * TM >= cnt) return;   // consumers of this tile also early-return
        #pragma unroll 4
        for (int idx = tid; idx < TM * (K_ / 8); idx += 512) {
            int j = t * TM + (idx >> 7);
            int jj = (j < cnt) ? j : cnt - 1;   // clamp (matches consumer clamp)
            int u = idx & 127;
            int src = g_idx[b * S_ + jj];
            const float4* sp =
                (const float4*)(keys + ((size_t)b * S_ + src) * K_ + u * 8);
            __half hv[8];
            pack8h(hv, sp[0], sp[1]);
            *(uint4*)(g_keys_h + ((size_t)b * S_ + jj) * K_ + u * 8) = *(uint4*)hv;
        }
        __threadfence();     // tile globally visible before flag release
        __syncthreads();
        if (tid == 0) atomicExch(&g_tile_flag[bidx], 1);
        return;
    }

    // ================= scores role =================
    int sidx = bidx - NTILES;
    int half = sidx & 1;               // interleaved: both halves of a tile adjacent
    int tile = sidx >> 1;
    int b = tile / TILES_PER_B;
    int t = tile % TILES_PER_B;
    int cnt = g_cnt[b];
    if (t * TM >= cnt) return;

    // acquire: wait for this tile's gather (flag released after threadfence)
    if (tid == 0) {
        while (atomicAdd(&g_tile_flag[tile], 0) == 0) __nanosleep(64);
    }
    __syncthreads();

    uint32_t Aau[2], Bau[2];
    Aau[0] = (uint32_t)__cvta_generic_to_shared(dsmh);
    Aau[1] = Aau[0] + A_HALFS * 2;
    Bau[0] = Aau[0] + 2 * A_HALFS * 2;
    Bau[1] = Bau[0] + B_HALFS * 2;

    int warp = tid >> 5, lane = tid & 31;
    int wm = warp >> 2, wn = warp & 3;     // 4x4 warp grid
    int t4 = lane & 3, q8 = lane >> 2;
    int u8 = tid & 7;

    if (tid < TM) sscore[tid] = 0.f;

    int jrow[2];
    #pragma unroll
    for (int i = 0; i < 2; i++) {
        int j = t * TM + i * 64 + (tid >> 3);
        jrow[i] = (j < cnt) ? j : cnt - 1;
    }
    const __half* arow[2];
    #pragma unroll
    for (int i = 0; i < 2; i++)
        arow[i] = g_keys_h + ((size_t)b * S_ + jrow[i]) * K_;

    uint32_t a_lm = (uint32_t)((wm * 32 + (lane & 15)) * SSTRH + (lane >> 4) * 8) * 2u;
    uint32_t b_lm = (uint32_t)((wn * 64 + (lane & 7) + ((lane >> 4) << 3)) * SSTRH +
                               ((lane >> 3) & 1) * 8) * 2u;

    float sacc[4] = {0.f, 0.f, 0.f, 0.f};
    float c[2][8][4];

#define LOAD_CHUNK(bufi, col0)                                                  \
    do {                                                                        \
        _Pragma("unroll") for (int i = 0; i < 2; i++) {                         \
            int r = i * 64 + (tid >> 3);                                        \
            cpa16s(Aau[bufi] + (uint32_t)(r * SSTRH + u8 * 8) * 2u,             \
                   arow[i] + (col0) + u8 * 8);                                  \
        }                                                                       \
        _Pragma("unroll") for (int i = 0; i < 4; i++) {                         \
            int r = i * 64 + (tid >> 3);                                        \
            cpa16s(Bau[bufi] + (uint32_t)(r * SSTRH + u8 * 8) * 2u,             \
                   brow[i] + (col0) + u8 * 8);                                  \
        }                                                                       \
    } while (0)

    #pragma unroll
    for (int hp = 0; hp < NPASS / HSPLIT; hp++) {
        int ht = half * (NPASS / HSPLIT) + hp;
        int h0 = ht * TN;
        __syncthreads();  // prev epilogue done with qs/vs
        if (tid < TN) {
            qs[tid] = g_qproj[b * H_ + h0 + tid];
            vs[tid] = v_w[h0 + tid];
        }
        const __half* brow[4];
        #pragma unroll
        for (int i = 0; i < 4; i++)
            brow[i] = g_wk_h + (size_t)(h0 + i * 64 + (tid >> 3)) * K_;

        #pragma unroll
        for (int mt = 0; mt < 2; mt++)
            #pragma unroll
            for (int nt = 0; nt < 8; nt++)
                #pragma unroll
                for (int j = 0; j < 4; j++) c[mt][nt][j] = 0.f;

        LOAD_CHUNK(0, 0);
        cp_commit();

        for (int kc = 0; kc < NCHUNK; kc++) {
            int buf = kc & 1;
            if (kc + 1 < NCHUNK) {
                LOAD_CHUNK(buf ^ 1, (kc + 1) * KCH);
                cp_commit();
                cp_wait<1>();
            } else {
                cp_wait<0>();
            }
            __syncthreads();

            #pragma unroll
            for (int kst = 0; kst < 4; kst++) {
                uint32_t koffB = (uint32_t)(kst * 16) * 2u;
                uint32_t a[2][4];
                ldsm_x4(a[0], Aau[buf] + a_lm + koffB);
                ldsm_x4(a[1], Aau[buf] + a_lm + (uint32_t)(16 * SSTRH) * 2u + koffB);
                uint32_t bf[4][4];
                #pragma unroll
                for (int p = 0; p < 4; p++)
                    ldsm_x4(bf[p], Bau[buf] + b_lm +
                                   (uint32_t)(p * 16 * SSTRH) * 2u + koffB);
                #pragma unroll
                for (int mt = 0; mt < 2; mt++)
                    #pragma unroll
                    for (int nt = 0; nt < 8; nt++)
                        mma16816(c[mt][nt], a[mt],
                                 bf[nt >> 1][(nt & 1) * 2],
                                 bf[nt >> 1][(nt & 1) * 2 + 1]);
            }
            __syncthreads();
        }

        // fused epilogue: sacc += tanh(c + q_proj) * v_w
        #pragma unroll
        for (int mt = 0; mt < 2; mt++) {
            #pragma unroll
            for (int nt = 0; nt < 8; nt++) {
                int col = wn * 64 + nt * 8 + t4 * 2;
                float q0 = qs[col], q1 = qs[col + 1];
                float v0 = vs[col], v1 = vs[col + 1];
                sacc[mt * 2 + 0] = fmaf(tanh_mufu(c[mt][nt][0] + q0), v0,
                                   fmaf(tanh_mufu(c[mt][nt][1] + q1), v1, sacc[mt * 2 + 0]));
                sacc[mt * 2 + 1] = fmaf(tanh_mufu(c[mt][nt][2] + q0), v0,
                                   fmaf(tanh_mufu(c[mt][nt][3] + q1), v1, sacc[mt * 2 + 1]));
            }
        }
    }

    #pragma unroll
    for (int i = 0; i < 4; i++) {
        sacc[i] += __shfl_xor_sync(0xffffffffu, sacc[i], 1);
        sacc[i] += __shfl_xor_sync(0xffffffffu, sacc[i], 2);
    }
    __syncthreads();
    if (t4 == 0) {
        int r = wm * 32 + q8;
        atomicAdd(&sscore[r],      sacc[0]);
        atomicAdd(&sscore[r + 8],  sacc[1]);
        atomicAdd(&sscore[r + 16], sacc[2]);
        atomicAdd(&sscore[r + 24], sacc[3]);
    }
    __syncthreads();
    if (tid < TM) {
        int j = t * TM + tid;
        // exactly 2 fp32 contributions per row onto 0 -> commutative, deterministic
        if (j < cnt) atomicAdd(&g_scores[b * S_ + g_idx[b * S_ + j]], sscore[tid]);
    }
#undef LOAD_CHUNK
}

// ---------------- kernel 3: one-pass masked softmax (1024 thr, regs-resident) ---
__global__ __launch_bounds__(1024) void softmax_kernel(float* __restrict__ w_out) {
    __shared__ float redm[32];
    __shared__ float reds[32];
    __shared__ float bmax, bsum;
    int b = blockIdx.x, tid = threadIdx.x;
    int warp = tid >> 5, lane = tid & 31;
    const float* sc = g_scores + b * S_;

    float v[4];
    #pragma unroll
    for (int i = 0; i < 4; i++) v[i] = sc[tid + i * 1024];

    float m = fmaxf(fmaxf(v[0], v[1]), fmaxf(v[2], v[3]));
    #pragma unroll
    for (int o = 16; o; o >>= 1) m = fmaxf(m, __shfl_xor_sync(0xffffffffu, m, o));
    if (lane == 0) redm[warp] = m;
    __syncthreads();
    if (warp == 0) {
        float x = redm[lane];
        #pragma unroll
        for (int o = 16; o; o >>= 1) x = fmaxf(x, __shfl_xor_sync(0xffffffffu, x, o));
        if (lane == 0) bmax = x;
    }
    __syncthreads();
    float mm = bmax;

    float e[4], sum = 0.f;
    #pragma unroll
    for (int i = 0; i < 4; i++) {
        e[i] = expf(v[i] - mm);   // masked (-inf) -> 0
        sum += e[i];
    }
    #pragma unroll
    for (int o = 16; o; o >>= 1) sum += __shfl_xor_sync(0xffffffffu, sum, o);
    if (lane == 0) reds[warp] = sum;
    __syncthreads();
    if (warp == 0) {
        float x = reds[lane];
        #pragma unroll
        for (int o = 16; o; o >>= 1) x += __shfl_xor_sync(0xffffffffu, x, o);
        if (lane == 0) bsum = x;
    }
    __syncthreads();
    float inv = 1.0f / bsum;

    float* wbuf = w_out + b * S_;
    #pragma unroll
    for (int i = 0; i < 4; i++) wbuf[tid + i * 1024] = e[i] * inv;
}

// ---------------- kernel 4: context = attn @ values (linear, skip w==0) ---------
__global__ void context_part_kernel(const float* __restrict__ values,
                                    const float* __restrict__ w) {
    int b = blockIdx.x >> 7;
    int p = blockIdx.x & 127;
    int tid = threadIdx.x;
    int s0 = p * (S_ / CSPLIT);   // 32 rows per split
    const float4* vp = (const float4*)(values + ((size_t)b * S_ + s0) * V_) + tid;
    const float* wb = w + b * S_ + s0;
    float4 acc = make_float4(0.f, 0.f, 0.f, 0.f);
    #pragma unroll 4
    for (int s = 0; s < S_ / CSPLIT; s++) {
        float ws = __ldg(wb + s);
        if (ws != 0.f) {   // masked rows have weight exactly 0 -> skip values read
            float4 v = ldcs4(vp + (size_t)s * (V_ / 4));   // streaming: no reuse
            acc.x += ws * v.x; acc.y += ws * v.y;
            acc.z += ws * v.z; acc.w += ws * v.w;
        }
    }
    ((float4*)g_ctx_part)[((size_t)p * B_ + b) * (V_ / 4) + tid] = acc;
}

// grid B*4: each block covers 256 columns; ILP-4 over 128 partials
__global__ void context_reduce_kernel(float* __restrict__ ctx) {
    int b = blockIdx.x >> 2;
    int q = blockIdx.x & 3;
    int col = q * 256 + threadIdx.x;
    float s0 = 0.f, s1 = 0.f, s2 = 0.f, s3 = 0.f;
    #pragma unroll 8
    for (int p = 0; p < CSPLIT; p += 4) {
        s0 += g_ctx_part[((size_t)(p + 0) * B_ + b) * V_ + col];
        s1 += g_ctx_part[((size_t)(p + 1) * B_ + b) * V_ + col];
        s2 += g_ctx_part[((size_t)(p + 2) * B_ + b) * V_ + col];
        s3 += g_ctx_part[((size_t)(p + 3) * B_ + b) * V_ + col];
    }
    ctx[b * V_ + col] = (s0 + s1) + (s2 + s3);
}

// ---------------- launch ----------------
extern "C" void kernel_launch(void* const* d_in, const int* in_sizes, int n_in,
                              void* d_out, int out_size) {
    const float* query  = (const float*)d_in[0];
    const float* keys   = (const float*)d_in[1];
    const float* values = (const float*)d_in[2];
    const int*   mask   = (const int*)d_in[3];
    const float* Wq_w   = (const float*)d_in[4];
    const float* Wq_b   = (const float*)d_in[5];
    const float* Wk_w   = (const float*)d_in[6];
    const float* Wk_b   = (const float*)d_in[7];
    const float* v_w    = (const float*)d_in[8];
    (void)in_sizes; (void)n_in; (void)out_size;

    float* out     = (float*)d_out;
    float* out_ctx = out;             // context: [32,1024]
    float* out_w   = out + B_ * V_;   // attention_weights: [32,4096]

    cudaFuncSetAttribute(gs_kernel,
                         cudaFuncAttributeMaxDynamicSharedMemorySize, DSMEM_BYTES);

    setup_kernel<<<SETUP_BLOCKS, 256>>>(mask, Wk_w, query, Wq_w, Wq_b, Wk_b);
    gs_kernel<<<GS_BLOCKS, 512, DSMEM_BYTES>>>(keys, v_w);
    softmax_kernel<<<B_, 1024>>>(out_w);
    context_part_kernel<<<B_ * CSPLIT, 256>>>(values, out_w);
    context_reduce_kernel<<<B_ * 4, 256>>>(out_ctx);
}

// round 17
// speedup vs baseline: 1.0887x; 1.0887x over previous
#include <cuda_runtime.h>
#include <cuda_fp16.h>
#include <cstdint>

#define B_ 32
#define S_ 4096
#define K_ 1024
#define H_ 1024
#define V_ 1024

#define TM 128             // compacted rows per block
#define TN 256             // h columns per pass
#define NPASS (H_ / TN)    // 4
#define HSPLIT 2           // h-passes split across 2 blocks (score is additive in h)
#define KCH 64             // k halves per chunk (128B rows)
#define NCHUNK (K_ / KCH)  // 16
#define NSTAGE 4           // cp.async ring depth (compile-time slots: kc & 3)
#define SSTRH 72           // smem row stride in halves (64 data + 8 pad = 144B)
#define CSPLIT 128
#define TILES_PER_B (S_ / TM)  // 32

#define A_HALFS (TM * SSTRH)   // 9216
#define B_HALFS (TN * SSTRH)   // 18432
#define STAGE_HALFS (A_HALFS + B_HALFS)
#define DSMEM_BYTES (NSTAGE * STAGE_HALFS * 2)  // 221184 B

// fused setup grid split: compact | convert Wk | qproj (mutually independent)
#define COMPACT_BLOCKS 32
#define CONV_BLOCKS    ((H_ * K_) / (256 * 8))   // 512
#define QPROJ_BLOCKS   (B_ * (H_ / 128))         // 256
#define SETUP_BLOCKS (COMPACT_BLOCKS + CONV_BLOCKS + QPROJ_BLOCKS)

// ---------------- scratch ----------------
__device__ float  g_qproj[B_ * H_];
__device__ float  g_scores[B_ * S_];
__device__ float  g_ctx_part[CSPLIT * B_ * V_];
__device__ int    g_idx[B_ * S_];          // compacted unmasked row indices
__device__ int    g_cnt[B_];               // unmasked count per batch
__device__ __half g_keys_h[B_ * S_ * K_];  // gathered fp16 keys (compacted rows)
__device__ __half g_wk_h[H_ * K_];         // fp16 Wk

// ---------------- helpers ----------------
__device__ __forceinline__ void cpa16s(uint32_t s, const void* g) {
    asm volatile("cp.async.cg.shared.global [%0], [%1], 16;" :: "r"(s), "l"(g));
}
__device__ __forceinline__ void cp_commit() { asm volatile("cp.async.commit_group;"); }
template <int N> __device__ __forceinline__ void cp_wait() {
    asm volatile("cp.async.wait_group %0;" :: "n"(N));
}
__device__ __forceinline__ float tanh_mufu(float x) {
    float y;
    asm("tanh.approx.f32 %0, %1;" : "=f"(y) : "f"(x));
    return y;
}
__device__ __forceinline__ void ldsm_x4(uint32_t r[4], uint32_t addr) {
    asm volatile("ldmatrix.sync.aligned.m8n8.x4.shared.b16 {%0,%1,%2,%3}, [%4];"
                 : "=r"(r[0]), "=r"(r[1]), "=r"(r[2]), "=r"(r[3]) : "r"(addr));
}
__device__ __forceinline__ void mma16816(float c[4], const uint32_t a[4],
                                         uint32_t b0, uint32_t b1) {
    asm volatile(
        "mma.sync.aligned.m16n8k16.row.col.f32.f16.f16.f32 "
        "{%0,%1,%2,%3}, {%4,%5,%6,%7}, {%8,%9}, {%0,%1,%2,%3};"
        : "+f"(c[0]), "+f"(c[1]), "+f"(c[2]), "+f"(c[3])
        : "r"(a[0]), "r"(a[1]), "r"(a[2]), "r"(a[3]), "r"(b0), "r"(b1));
}
__device__ __forceinline__ void pack8h(__half* dst, const float4 a, const float4 b) {
    __half2* d = (__half2*)dst;
    d[0] = __floats2half2_rn(a.x, a.y);
    d[1] = __floats2half2_rn(a.z, a.w);
    d[2] = __floats2half2_rn(b.x, b.y);
    d[3] = __floats2half2_rn(b.z, b.w);
}
__device__ __forceinline__ float4 ldcs4(const float4* p) {
    float4 v;
    asm volatile("ld.global.cs.v4.f32 {%0,%1,%2,%3}, [%4];"
                 : "=f"(v.x), "=f"(v.y), "=f"(v.z), "=f"(v.w) : "l"(p));
    return v;
}

// ---------------- kernel 0: fused setup (compact | convert Wk | qproj) ----------
__global__ void setup_kernel(const int* __restrict__ mask,
                             const float* __restrict__ Wk,
                             const float* __restrict__ query,
                             const float* __restrict__ Wq_w,
                             const float* __restrict__ Wq_b,
                             const float* __restrict__ Wk_b) {
    __shared__ float4 q4[K_ / 4];   // qproj segment
    __shared__ int wsum[8];         // compact segment
    __shared__ int sbase;
    int bid = blockIdx.x, tid = threadIdx.x;

    if (bid < COMPACT_BLOCKS) {
        // ---- fill scores (0 / -inf) + deterministic compact ----
        int b = bid, warp = tid >> 5, lane = tid & 31;
        if (tid == 0) sbase = 0;
        __syncthreads();
        const int* mb = mask + b * S_;
        for (int it = 0; it < S_ / 256; it++) {
            int s = it * 256 + tid;
            int m = (mb[s] != 0);
            // unmasked rows start at 0 (split-H partials atomicAdd onto this)
            g_scores[b * S_ + s] = m ? 0.0f : __int_as_float(0xff800000);
            unsigned bal = __ballot_sync(0xffffffffu, m);
            int pre = __popc(bal & ((1u << lane) - 1));
            if (lane == 0) wsum[warp] = __popc(bal);
            __syncthreads();
            int wpre = 0;
            #pragma unroll
            for (int w = 0; w < 8; w++) if (w < warp) wpre += wsum[w];
            if (m) g_idx[b * S_ + sbase + wpre + pre] = s;
            __syncthreads();
            if (tid == 0) {
                int t = 0;
                #pragma unroll
                for (int w = 0; w < 8; w++) t += wsum[w];
                sbase += t;
            }
            __syncthreads();
        }
        if (tid == 0) g_cnt[b] = sbase;
    } else if (bid < COMPACT_BLOCKS + CONV_BLOCKS) {
        // ---- Wk -> fp16 ----
        int i = (bid - COMPACT_BLOCKS) * 256 + tid;
        const float4* sp = (const float4*)(Wk + (size_t)i * 8);
        __half hv[8];
        pack8h(hv, sp[0], sp[1]);
        *(uint4*)(g_wk_h + (size_t)i * 8) = *(uint4*)hv;
    } else {
        // ---- q_proj (fp32 exact, biases folded), float4 + 2-row ILP ----
        int qb = bid - COMPACT_BLOCKS - CONV_BLOCKS;
        int b = qb >> 3, hbase = (qb & 7) * 128;
        for (int i = tid; i < K_ / 4; i += 256)
            q4[i] = ((const float4*)(query + b * K_))[i];
        __syncthreads();
        int warp = tid >> 5, lane = tid & 31;
        #pragma unroll 1
        for (int i = 0; i < 16; i += 2) {
            int h0 = hbase + warp * 16 + i;
            const float4* w0 = (const float4*)(Wq_w + (size_t)h0 * K_);
            const float4* w1 = (const float4*)(Wq_w + (size_t)(h0 + 1) * K_);
            float4 a0 = make_float4(0.f, 0.f, 0.f, 0.f);
            float4 a1 = make_float4(0.f, 0.f, 0.f, 0.f);
            #pragma unroll
            for (int it = 0; it < 8; it++) {
                int kk = it * 32 + lane;
                float4 qv = q4[kk];
                float4 x0 = w0[kk];
                float4 x1 = w1[kk];
                a0.x = fmaf(qv.x, x0.x, a0.x); a0.y = fmaf(qv.y, x0.y, a0.y);
                a0.z = fmaf(qv.z, x0.z, a0.z); a0.w = fmaf(qv.w, x0.w, a0.w);
                a1.x = fmaf(qv.x, x1.x, a1.x); a1.y = fmaf(qv.y, x1.y, a1.y);
                a1.z = fmaf(qv.z, x1.z, a1.z); a1.w = fmaf(qv.w, x1.w, a1.w);
            }
            float s0 = (a0.x + a0.y) + (a0.z + a0.w);
            float s1 = (a1.x + a1.y) + (a1.z + a1.w);
            #pragma unroll
            for (int o = 16; o; o >>= 1) {
                s0 += __shfl_xor_sync(0xffffffffu, s0, o);
                s1 += __shfl_xor_sync(0xffffffffu, s1, o);
            }
            if (lane == 0) {
                g_qproj[b * H_ + h0]     = s0 + Wq_b[h0]     + Wk_b[h0];
                g_qproj[b * H_ + h0 + 1] = s1 + Wq_b[h0 + 1] + Wk_b[h0 + 1];
            }
        }
    }
}

// ---------------- kernel 0c: gather unmasked keys rows -> fp16 compacted --------
__global__ void gather_keys_kernel(const float* __restrict__ keys) {
    int b = blockIdx.x / TILES_PER_B;
    int t = blockIdx.x % TILES_PER_B;
    int cnt = g_cnt[b];
    if (t * TM >= cnt) return;
    int tid = threadIdx.x;
    for (int idx = tid; idx < TM * (K_ / 8); idx += 256) {
        int j = t * TM + (idx >> 7);
        if (j >= cnt) break;
        int u = idx & 127;
        int src = g_idx[b * S_ + j];
        const float4* sp = (const float4*)(keys + ((size_t)b * S_ + src) * K_ + u * 8);
        __half hv[8];
        pack8h(hv, sp[0], sp[1]);
        *(uint4*)(g_keys_h + ((size_t)b * S_ + j) * K_ + u * 8) = *(uint4*)hv;
    }
}

// ---------------- kernel 2: fused k_proj + tanh + v_w, fp16 LDSM ----------------
// 512 threads = 16 warps in 4(m) x 4(n) grid; warp tile 32x64; TM=128 x TN=256.
// SPLIT-H (R11) + 4-stage cp.async ring with COMPILE-TIME slots (kc & 3 in a
// fully-unrolled 16-iter loop) and ONE __syncthreads per chunk.
__global__ __launch_bounds__(512, 1) void scores_kernel(const float* __restrict__ v_w) {
    extern __shared__ __half dsmh[];
    __shared__ float qs[TN];
    __shared__ float vs[TN];
    __shared__ float sscore[TM];

    int bidx = blockIdx.x;
    int half = bidx & 1;               // interleaved: both halves of a tile adjacent
    int tile = bidx >> 1;
    int b = tile / TILES_PER_B;
    int t = tile % TILES_PER_B;
    int cnt = g_cnt[b];
    if (t * TM >= cnt) return;

    uint32_t base = (uint32_t)__cvta_generic_to_shared(dsmh);
    uint32_t Aau[NSTAGE], Bau[NSTAGE];
    #pragma unroll
    for (int i = 0; i < NSTAGE; i++) {
        Aau[i] = base + (uint32_t)(i * STAGE_HALFS) * 2u;
        Bau[i] = Aau[i] + A_HALFS * 2;
    }

    int tid = threadIdx.x, warp = tid >> 5, lane = tid & 31;
    int wm = warp >> 2, wn = warp & 3;     // 4x4 warp grid
    int t4 = lane & 3, q8 = lane >> 2;
    int u8 = tid & 7;

    if (tid < TM) sscore[tid] = 0.f;

    int jrow[2];
    #pragma unroll
    for (int i = 0; i < 2; i++) {
        int j = t * TM + i * 64 + (tid >> 3);
        jrow[i] = (j < cnt) ? j : cnt - 1;
    }
    const __half* arow[2];
    #pragma unroll
    for (int i = 0; i < 2; i++)
        arow[i] = g_keys_h + ((size_t)b * S_ + jrow[i]) * K_;

    uint32_t a_lm = (uint32_t)((wm * 32 + (lane & 15)) * SSTRH + (lane >> 4) * 8) * 2u;
    uint32_t b_lm = (uint32_t)((wn * 64 + (lane & 7) + ((lane >> 4) << 3)) * SSTRH +
                               ((lane >> 3) & 1) * 8) * 2u;

    float sacc[4] = {0.f, 0.f, 0.f, 0.f};
    float c[2][8][4];

#define LOAD_CHUNK(bufi, col0)                                                  \
    do {                                                                        \
        _Pragma("unroll") for (int i = 0; i < 2; i++) {                         \
            int r = i * 64 + (tid >> 3);                                        \
            cpa16s(Aau[bufi] + (uint32_t)(r * SSTRH + u8 * 8) * 2u,             \
                   arow[i] + (col0) + u8 * 8);                                  \
        }                                                                       \
        _Pragma("unroll") for (int i = 0; i < 4; i++) {                         \
            int r = i * 64 + (tid >> 3);                                        \
            cpa16s(Bau[bufi] + (uint32_t)(r * SSTRH + u8 * 8) * 2u,             \
                   brow[i] + (col0) + u8 * 8);                                  \
        }                                                                       \
        cp_commit();                                                            \
    } while (0)

    #pragma unroll
    for (int hp = 0; hp < NPASS / HSPLIT; hp++) {
        int ht = half * (NPASS / HSPLIT) + hp;
        int h0 = ht * TN;
        __syncthreads();  // prev epilogue done with qs/vs; all slots drained
        if (tid < TN) {
            qs[tid] = g_qproj[b * H_ + h0 + tid];
            vs[tid] = v_w[h0 + tid];
        }
        const __half* brow[4];
        #pragma unroll
        for (int i = 0; i < 4; i++)
            brow[i] = g_wk_h + (size_t)(h0 + i * 64 + (tid >> 3)) * K_;

        #pragma unroll
        for (int mt = 0; mt < 2; mt++)
            #pragma unroll
            for (int nt = 0; nt < 8; nt++)
                #pragma unroll
                for (int j = 0; j < 4; j++) c[mt][nt][j] = 0.f;

        // 4-stage prologue: chunks 0,1,2 -> slots 0,1,2
        LOAD_CHUNK(0, 0);
        LOAD_CHUNK(1, KCH);
        LOAD_CHUNK(2, 2 * KCH);

        #pragma unroll
        for (int kc = 0; kc < NCHUNK; kc++) {
            int buf = kc & 3;                    // compile-time after full unroll
            if (kc <= NCHUNK - 4)      cp_wait<2>();
            else if (kc == NCHUNK - 3) cp_wait<2>();
            else if (kc == NCHUNK - 2) cp_wait<1>();
            else                       cp_wait<0>();
            __syncthreads();  // chunk kc visible; all warps done computing kc-1
            if (kc + 3 < NCHUNK) {
                // overwrites slot of chunk kc-1 (compute ordered before this sync)
                LOAD_CHUNK((kc + 3) & 3, (kc + 3) * KCH);
            }

            #pragma unroll
            for (int kst = 0; kst < 4; kst++) {
                uint32_t koffB = (uint32_t)(kst * 16) * 2u;
                uint32_t a[2][4];
                ldsm_x4(a[0], Aau[buf] + a_lm + koffB);
                ldsm_x4(a[1], Aau[buf] + a_lm + (uint32_t)(16 * SSTRH) * 2u + koffB);
                uint32_t bf[4][4];
                #pragma unroll
                for (int p = 0; p < 4; p++)
                    ldsm_x4(bf[p], Bau[buf] + b_lm +
                                   (uint32_t)(p * 16 * SSTRH) * 2u + koffB);
                #pragma unroll
                for (int mt = 0; mt < 2; mt++)
                    #pragma unroll
                    for (int nt = 0; nt < 8; nt++)
                        mma16816(c[mt][nt], a[mt],
                                 bf[nt >> 1][(nt & 1) * 2],
                                 bf[nt >> 1][(nt & 1) * 2 + 1]);
            }
        }

        // fused epilogue: sacc += tanh(c + q_proj) * v_w
        #pragma unroll
        for (int mt = 0; mt < 2; mt++) {
            #pragma unroll
            for (int nt = 0; nt < 8; nt++) {
                int col = wn * 64 + nt * 8 + t4 * 2;
                float q0 = qs[col], q1 = qs[col + 1];
                float v0 = vs[col], v1 = vs[col + 1];
                sacc[mt * 2 + 0] = fmaf(tanh_mufu(c[mt][nt][0] + q0), v0,
                                   fmaf(tanh_mufu(c[mt][nt][1] + q1), v1, sacc[mt * 2 + 0]));
                sacc[mt * 2 + 1] = fmaf(tanh_mufu(c[mt][nt][2] + q0), v0,
                                   fmaf(tanh_mufu(c[mt][nt][3] + q1), v1, sacc[mt * 2 + 1]));
            }
        }
    }

    #pragma unroll
    for (int i = 0; i < 4; i++) {
        sacc[i] += __shfl_xor_sync(0xffffffffu, sacc[i], 1);
        sacc[i] += __shfl_xor_sync(0xffffffffu, sacc[i], 2);
    }
    __syncthreads();
    if (t4 == 0) {
        int r = wm * 32 + q8;
        atomicAdd(&sscore[r],      sacc[0]);
        atomicAdd(&sscore[r + 8],  sacc[1]);
        atomicAdd(&sscore[r + 16], sacc[2]);
        atomicAdd(&sscore[r + 24], sacc[3]);
    }
    __syncthreads();
    if (tid < TM) {
        int j = t * TM + tid;
        // exactly 2 fp32 contributions per row onto 0 -> commutative, deterministic
        if (j < cnt) atomicAdd(&g_scores[b * S_ + g_idx[b * S_ + j]], sscore[tid]);
    }
#undef LOAD_CHUNK
}

// ---------------- kernel 3: one-pass masked softmax (1024 thr, regs-resident) ---
__global__ __launch_bounds__(1024) void softmax_kernel(float* __restrict__ w_out) {
    __shared__ float redm[32];
    __shared__ float reds[32];
    __shared__ float bmax, bsum;
    int b = blockIdx.x, tid = threadIdx.x;
    int warp = tid >> 5, lane = tid & 31;
    const float* sc = g_scores + b * S_;

    float v[4];
    #pragma unroll
    for (int i = 0; i < 4; i++) v[i] = sc[tid + i * 1024];

    float m = fmaxf(fmaxf(v[0], v[1]), fmaxf(v[2], v[3]));
    #pragma unroll
    for (int o = 16; o; o >>= 1) m = fmaxf(m, __shfl_xor_sync(0xffffffffu, m, o));
    if (lane == 0) redm[warp] = m;
    __syncthreads();
    if (warp == 0) {
        float x = redm[lane];
        #pragma unroll
        for (int o = 16; o; o >>= 1) x = fmaxf(x, __shfl_xor_sync(0xffffffffu, x, o));
        if (lane == 0) bmax = x;
    }
    __syncthreads();
    float mm = bmax;

    float e[4], sum = 0.f;
    #pragma unroll
    for (int i = 0; i < 4; i++) {
        e[i] = expf(v[i] - mm);   // masked (-inf) -> 0
        sum += e[i];
    }
    #pragma unroll
    for (int o = 16; o; o >>= 1) sum += __shfl_xor_sync(0xffffffffu, sum, o);
    if (lane == 0) reds[warp] = sum;
    __syncthreads();
    if (warp == 0) {
        float x = reds[lane];
        #pragma unroll
        for (int o = 16; o; o >>= 1) x += __shfl_xor_sync(0xffffffffu, x, o);
        if (lane == 0) bsum = x;
    }
    __syncthreads();
    float inv = 1.0f / bsum;

    float* wbuf = w_out + b * S_;
    #pragma unroll
    for (int i = 0; i < 4; i++) wbuf[tid + i * 1024] = e[i] * inv;
}

// ---------------- kernel 4: context = attn @ values (linear, skip w==0) ---------
__global__ void context_part_kernel(const float* __restrict__ values,
                                    const float* __restrict__ w) {
    int b = blockIdx.x >> 7;
    int p = blockIdx.x & 127;
    int tid = threadIdx.x;
    int s0 = p * (S_ / CSPLIT);   // 32 rows per split
    const float4* vp = (const float4*)(values + ((size_t)b * S_ + s0) * V_) + tid;
    const float* wb = w + b * S_ + s0;
    float4 acc = make_float4(0.f, 0.f, 0.f, 0.f);
    #pragma unroll 4
    for (int s = 0; s < S_ / CSPLIT; s++) {
        float ws = __ldg(wb + s);
        if (ws != 0.f) {   // masked rows have weight exactly 0 -> skip values read
            float4 v = ldcs4(vp + (size_t)s * (V_ / 4));   // streaming: no reuse
            acc.x += ws * v.x; acc.y += ws * v.y;
            acc.z += ws * v.z; acc.w += ws * v.w;
        }
    }
    ((float4*)g_ctx_part)[((size_t)p * B_ + b) * (V_ / 4) + tid] = acc;
}

// grid B*4: each block covers 256 columns; ILP-4 over 128 partials
__global__ void context_reduce_kernel(float* __restrict__ ctx) {
    int b = blockIdx.x >> 2;
    int q = blockIdx.x & 3;
    int col = q * 256 + threadIdx.x;
    float s0 = 0.f, s1 = 0.f, s2 = 0.f, s3 = 0.f;
    #pragma unroll 8
    for (int p = 0; p < CSPLIT; p += 4) {
        s0 += g_ctx_part[((size_t)(p + 0) * B_ + b) * V_ + col];
        s1 += g_ctx_part[((size_t)(p + 1) * B_ + b) * V_ + col];
        s2 += g_ctx_part[((size_t)(p + 2) * B_ + b) * V_ + col];
        s3 += g_ctx_part[((size_t)(p + 3) * B_ + b) * V_ + col];
    }
    ctx[b * V_ + col] = (s0 + s1) + (s2 + s3);
}

// ---------------- launch ----------------
extern "C" void kernel_launch(void* const* d_in, const int* in_sizes, int n_in,
                              void* d_out, int out_size) {
    const float* query  = (const float*)d_in[0];
    const float* keys   = (const float*)d_in[1];
    const float* values = (const float*)d_in[2];
    const int*   mask   = (const int*)d_in[3];
    const float* Wq_w   = (const float*)d_in[4];
    const float* Wq_b   = (const float*)d_in[5];
    const float* Wk_w   = (const float*)d_in[6];
    const float* Wk_b   = (const float*)d_in[7];
    const float* v_w    = (const float*)d_in[8];
    (void)in_sizes; (void)n_in; (void)out_size;

    float* out     = (float*)d_out;
    float* out_ctx = out;             // context: [32,1024]
    float* out_w   = out + B_ * V_;   // attention_weights: [32,4096]

    cudaFuncSetAttribute(scores_kernel,
                         cudaFuncAttributeMaxDynamicSharedMemorySize, DSMEM_BYTES);

    setup_kernel<<<SETUP_BLOCKS, 256>>>(mask, Wk_w, query, Wq_w, Wq_b, Wk_b);
    gather_keys_kernel<<<B_ * TILES_PER_B, 256>>>(keys);
    scores_kernel<<<B_ * TILES_PER_B * HSPLIT, 512, DSMEM_BYTES>>>(v_w);
    softmax_kernel<<<B_, 1024>>>(out_w);
    context_part_kernel<<<B_ * CSPLIT, 256>>>(values, out_w);
    context_reduce_kernel<<<B_ * 4, 256>>>(out_ctx);
}